// round 1
// baseline (speedup 1.0000x reference)
#include <cuda_runtime.h>
#include <math.h>

#define SEQ  4096
#define NH   16
#define HD   64
#define HID  1024

// Scratch (no allocation allowed) — device globals.
__device__ float g_qkv[SEQ * 3 * HID];      // 48 MB
__device__ float g_Q[NH * SEQ * HD];        // 16 MB
__device__ float g_K[NH * SEQ * HD];        // 16 MB
__device__ float g_V[NH * SEQ * HD];        // 16 MB
__device__ float g_ctx[SEQ * HID];          // 16 MB

// ---------------------------------------------------------------------------
// SGEMM: C[M,N] = A[M,K] @ B[K,N] + bias[N]   (fp32, 128x128x8 tiles)
// ---------------------------------------------------------------------------
__global__ __launch_bounds__(256) void sgemm_kernel(
    const float* __restrict__ A, const float* __restrict__ B,
    const float* __restrict__ bias, float* __restrict__ C,
    int M, int N, int K)
{
    __shared__ float As[8][128];   // transposed A tile: As[k][m]
    __shared__ float Bs[8][128];   // Bs[k][n]

    const int tid = threadIdx.x;
    const int tx  = tid & 15;       // 0..15 -> N micro
    const int ty  = tid >> 4;       // 0..15 -> M micro
    const int bx  = blockIdx.x;     // N tile
    const int by  = blockIdx.y;     // M tile

    const int a_row = tid >> 1;          // 0..127
    const int a_col = (tid & 1) * 4;     // 0 or 4
    const int b_row = tid >> 5;          // 0..7
    const int b_col = (tid & 31) * 4;    // 0..124

    const float* Ab = A + (size_t)(by * 128) * K;
    const float* Bb = B + bx * 128;

    float acc[8][8];
#pragma unroll
    for (int i = 0; i < 8; i++)
#pragma unroll
        for (int j = 0; j < 8; j++) acc[i][j] = 0.0f;

    for (int k0 = 0; k0 < K; k0 += 8) {
        float4 av = *(const float4*)(Ab + (size_t)a_row * K + k0 + a_col);
        float4 bv = *(const float4*)(Bb + (size_t)(k0 + b_row) * N + b_col);

        __syncthreads();   // previous iteration's compute done before overwrite
        As[a_col + 0][a_row] = av.x;
        As[a_col + 1][a_row] = av.y;
        As[a_col + 2][a_row] = av.z;
        As[a_col + 3][a_row] = av.w;
        *(float4*)&Bs[b_row][b_col] = bv;
        __syncthreads();

#pragma unroll
        for (int kk = 0; kk < 8; kk++) {
            float ra[8], rb[8];
            *(float4*)&ra[0] = *(const float4*)&As[kk][ty * 8];
            *(float4*)&ra[4] = *(const float4*)&As[kk][ty * 8 + 4];
            *(float4*)&rb[0] = *(const float4*)&Bs[kk][tx * 8];
            *(float4*)&rb[4] = *(const float4*)&Bs[kk][tx * 8 + 4];
#pragma unroll
            for (int i = 0; i < 8; i++)
#pragma unroll
                for (int j = 0; j < 8; j++)
                    acc[i][j] = fmaf(ra[i], rb[j], acc[i][j]);
        }
    }

    const int row0 = by * 128 + ty * 8;
    const int col0 = bx * 128 + tx * 8;
#pragma unroll
    for (int i = 0; i < 8; i++) {
        float* crow = C + (size_t)(row0 + i) * N + col0;
#pragma unroll
        for (int j = 0; j < 8; j++)
            crow[j] = acc[i][j] + bias[col0 + j];
    }
}

// ---------------------------------------------------------------------------
// RoPE + permute: g_qkv[s][3][h][d] -> g_Q/g_K/g_V [h][s][d]
// Q gets the 1/sqrt(HD) softmax scale folded in.
// ---------------------------------------------------------------------------
__global__ __launch_bounds__(256) void rope_kernel(
    const float* __restrict__ cosp, const float* __restrict__ sinp)
{
    const int idx = blockIdx.x * 256 + threadIdx.x;   // SEQ*NH*HD threads
    const int d = idx & 63;
    const int h = (idx >> 6) & 15;
    const int s = idx >> 10;

    const float c  = cosp[s * HD + d];
    const float sn = sinp[s * HD + d];

    const size_t base = (size_t)s * (3 * HID) + h * HD;
    const float q = g_qkv[base + d];
    const float k = g_qkv[base + HID + d];
    const float v = g_qkv[base + 2 * HID + d];

    const int   d2   = (d + 32) & 63;
    const float sign = (d < 32) ? -1.0f : 1.0f;
    const float qr = sign * g_qkv[base + d2];
    const float kr = sign * g_qkv[base + HID + d2];

    const size_t o = ((size_t)h * SEQ + s) * HD + d;
    g_Q[o] = (q * c + qr * sn) * 0.125f;   // 1/sqrt(64)
    g_K[o] = k * c + kr * sn;
    g_V[o] = v;
}

// ---------------------------------------------------------------------------
// Flash attention (fp32, online softmax). Block = (head, 64 q rows),
// 256 threads (16x16), each thread owns a 4x4 micro-tile.
// Smem: QsT[d][r], KsT[d][c] (reused as PsT[c][r]), Vs[c][d]  => 48 KB.
// XOR swizzle col^(row&60) keeps STS/LDS bank conflicts <= 2-way.
// ---------------------------------------------------------------------------
__global__ __launch_bounds__(256) void flash_kernel()
{
    __shared__ float Qs[64][64];   // [d][r], swizzled
    __shared__ float Ks[64][64];   // [d][c], swizzled; reused as Ps[c][r]
    __shared__ float Vs[64][64];   // [c][d], natural

    const int h  = blockIdx.y;
    const int qb = blockIdx.x;
    const int tid = threadIdx.x;
    const int tx = tid & 15;       // cols (c for S, d for O)
    const int ty = tid >> 4;       // rows (r)

    const float* Qg = g_Q + ((size_t)h * SEQ + qb * 64) * HD;
    const float* Kg = g_K + (size_t)h * SEQ * HD;
    const float* Vg = g_V + (size_t)h * SEQ * HD;

    // Load Q tile (transposed + swizzled)
#pragma unroll
    for (int i = 0; i < 4; i++) {
        const int vi = tid + i * 256;
        const int r = vi >> 4;
        const int d0 = (vi & 15) * 4;
        float4 q = *(const float4*)(Qg + r * HD + d0);
        Qs[d0 + 0][r ^ ((d0 + 0) & 60)] = q.x;
        Qs[d0 + 1][r ^ ((d0 + 1) & 60)] = q.y;
        Qs[d0 + 2][r ^ ((d0 + 2) & 60)] = q.z;
        Qs[d0 + 3][r ^ ((d0 + 3) & 60)] = q.w;
    }

    float m[4], l[4], O[4][4];
#pragma unroll
    for (int i = 0; i < 4; i++) {
        m[i] = -INFINITY;
        l[i] = 0.0f;
#pragma unroll
        for (int j = 0; j < 4; j++) O[i][j] = 0.0f;
    }

    for (int jt = 0; jt < SEQ / 64; jt++) {
        __syncthreads();   // everyone done with Ks(P)/Vs from prior iter
        // Load K (transposed+swizzled) and V (natural) tiles
#pragma unroll
        for (int i = 0; i < 4; i++) {
            const int vi = tid + i * 256;
            const int c = vi >> 4;
            const int d0 = (vi & 15) * 4;
            float4 k4 = *(const float4*)(Kg + (size_t)(jt * 64 + c) * HD + d0);
            Ks[d0 + 0][c ^ ((d0 + 0) & 60)] = k4.x;
            Ks[d0 + 1][c ^ ((d0 + 1) & 60)] = k4.y;
            Ks[d0 + 2][c ^ ((d0 + 2) & 60)] = k4.z;
            Ks[d0 + 3][c ^ ((d0 + 3) & 60)] = k4.w;
            float4 v4 = *(const float4*)(Vg + (size_t)(jt * 64 + c) * HD + d0);
            *(float4*)&Vs[c][d0] = v4;
        }
        __syncthreads();

        // S = Q @ K^T (scale already folded into Q)
        float S[4][4];
#pragma unroll
        for (int i = 0; i < 4; i++)
#pragma unroll
            for (int j = 0; j < 4; j++) S[i][j] = 0.0f;

#pragma unroll
        for (int dd = 0; dd < 64; dd++) {
            float4 qa = *(const float4*)&Qs[dd][(ty * 4) ^ (dd & 60)];
            float4 kb = *(const float4*)&Ks[dd][(tx * 4) ^ (dd & 60)];
            const float a0[4] = {qa.x, qa.y, qa.z, qa.w};
            const float b0[4] = {kb.x, kb.y, kb.z, kb.w};
#pragma unroll
            for (int i = 0; i < 4; i++)
#pragma unroll
                for (int j = 0; j < 4; j++)
                    S[i][j] = fmaf(a0[i], b0[j], S[i][j]);
        }

        // Online softmax (reduce across tx = low 4 lane bits)
        float alpha[4], P[4][4], rs[4];
#pragma unroll
        for (int i = 0; i < 4; i++) {
            float mt = fmaxf(fmaxf(S[i][0], S[i][1]), fmaxf(S[i][2], S[i][3]));
#pragma unroll
            for (int off = 1; off < 16; off <<= 1)
                mt = fmaxf(mt, __shfl_xor_sync(0xffffffffu, mt, off));
            const float mn = fmaxf(m[i], mt);
            alpha[i] = __expf(m[i] - mn);
            m[i] = mn;
            rs[i] = 0.0f;
#pragma unroll
            for (int j = 0; j < 4; j++) {
                P[i][j] = __expf(S[i][j] - mn);
                rs[i] += P[i][j];
            }
#pragma unroll
            for (int off = 1; off < 16; off <<= 1)
                rs[i] += __shfl_xor_sync(0xffffffffu, rs[i], off);
            l[i] = l[i] * alpha[i] + rs[i];
#pragma unroll
            for (int j = 0; j < 4; j++) O[i][j] *= alpha[i];
        }

        __syncthreads();   // all warps done reading Ks before P overwrite
        // Write P into Ks as PsT[c][r] (swizzled)
#pragma unroll
        for (int i = 0; i < 4; i++)
#pragma unroll
            for (int j = 0; j < 4; j++) {
                const int c = tx * 4 + j;
                const int r = ty * 4 + i;
                Ks[c][r ^ (c & 60)] = P[i][j];
            }
        __syncthreads();

        // O[r][d] += sum_c PsT[c][r] * Vs[c][d]
#pragma unroll
        for (int c = 0; c < 64; c++) {
            float4 pa = *(const float4*)&Ks[c][(ty * 4) ^ (c & 60)];
            float4 vb = *(const float4*)&Vs[c][tx * 4];
            const float p0[4] = {pa.x, pa.y, pa.z, pa.w};
            const float v0[4] = {vb.x, vb.y, vb.z, vb.w};
#pragma unroll
            for (int i = 0; i < 4; i++)
#pragma unroll
                for (int j = 0; j < 4; j++)
                    O[i][j] = fmaf(p0[i], v0[j], O[i][j]);
        }
    }

    // Epilogue: normalize and write ctx[s][h*64+d] (no permute needed later)
#pragma unroll
    for (int i = 0; i < 4; i++) {
        const float inv = 1.0f / l[i];
        const int s = qb * 64 + ty * 4 + i;
        float* crow = g_ctx + (size_t)s * HID + h * HD + tx * 4;
#pragma unroll
        for (int j = 0; j < 4; j++) crow[j] = O[i][j] * inv;
    }
}

// ---------------------------------------------------------------------------
// kernel_launch
// Inputs (metadata order): hidden_states, cu_seqlens(unused), cos, sin,
//                          W_qkv, b_qkv, W_proj, b_proj
// ---------------------------------------------------------------------------
extern "C" void kernel_launch(void* const* d_in, const int* in_sizes, int n_in,
                              void* d_out, int out_size)
{
    const float* hs    = (const float*)d_in[0];
    const float* cosp  = (const float*)d_in[2];
    const float* sinp  = (const float*)d_in[3];
    const float* Wqkv  = (const float*)d_in[4];
    const float* bqkv  = (const float*)d_in[5];
    const float* Wproj = (const float*)d_in[6];
    const float* bproj = (const float*)d_in[7];
    float* out = (float*)d_out;

    float *qkv_ptr, *ctx_ptr;
    cudaGetSymbolAddress((void**)&qkv_ptr, g_qkv);
    cudaGetSymbolAddress((void**)&ctx_ptr, g_ctx);

    // 1) QKV projection: [4096,1024] @ [1024,3072] + b
    sgemm_kernel<<<dim3(3 * HID / 128, SEQ / 128), 256>>>(
        hs, Wqkv, bqkv, qkv_ptr, SEQ, 3 * HID, HID);

    // 2) RoPE + permute to [h][s][d] (scale folded into Q)
    rope_kernel<<<(SEQ * NH * HD) / 256, 256>>>(cosp, sinp);

    // 3) Flash attention -> ctx[s][hid]
    flash_kernel<<<dim3(SEQ / 64, NH), 256>>>();

    // 4) Output projection: [4096,1024] @ [1024,1024] + b
    sgemm_kernel<<<dim3(HID / 128, SEQ / 128), 256>>>(
        ctx_ptr, Wproj, bproj, out, SEQ, HID, HID);
}

// round 3
// speedup vs baseline: 2.6739x; 2.6739x over previous
#include <cuda_runtime.h>
#include <math.h>
#include <stdint.h>

#define SEQ  4096
#define NH   16
#define HD   64
#define HID  1024

// Scratch (no allocation allowed) — device globals.
__device__ float g_qkv[SEQ * 3 * HID];
__device__ float g_Q[NH * SEQ * HD];     // [h][s][d]
__device__ float g_K[NH * SEQ * HD];     // [h][s][d]
__device__ float g_Vt[NH * HD * SEQ];    // [h][d][s]
__device__ float g_ctx[SEQ * HID];
__device__ float g_WqkvT[3 * HID * HID]; // [n][k]
__device__ float g_WprojT[HID * HID];    // [n][k]

// ---------------- helpers ----------------
__device__ __forceinline__ uint32_t f2tf_u(float x) {
    uint32_t r;
    asm("cvt.rna.tf32.f32 %0, %1;" : "=r"(r) : "f"(x));
    return r;
}
__device__ __forceinline__ float f2tf(float x) { return __uint_as_float(f2tf_u(x)); }

__device__ __forceinline__ void ldsm4(uint32_t& r0, uint32_t& r1, uint32_t& r2, uint32_t& r3,
                                      const void* p) {
    uint32_t addr = (uint32_t)__cvta_generic_to_shared(p);
    asm volatile("ldmatrix.sync.aligned.m8n8.x4.shared.b16 {%0,%1,%2,%3}, [%4];"
                 : "=r"(r0), "=r"(r1), "=r"(r2), "=r"(r3) : "r"(addr));
}

__device__ __forceinline__ void mma8(float c[4], const uint32_t a[4], uint32_t b0, uint32_t b1) {
    asm volatile(
        "mma.sync.aligned.m16n8k8.row.col.f32.tf32.tf32.f32 "
        "{%0,%1,%2,%3}, {%4,%5,%6,%7}, {%8,%9}, {%0,%1,%2,%3};"
        : "+f"(c[0]), "+f"(c[1]), "+f"(c[2]), "+f"(c[3])
        : "r"(a[0]), "r"(a[1]), "r"(a[2]), "r"(a[3]), "r"(b0), "r"(b1));
}

// ---------------------------------------------------------------------------
// Transpose: out[c][r] = in[r][c]
// ---------------------------------------------------------------------------
__global__ void transpose_kernel(const float* __restrict__ in, float* __restrict__ out,
                                 int R, int C) {
    __shared__ float t[32][33];
    const int bc = blockIdx.x * 32, br = blockIdx.y * 32;
    const int x = threadIdx.x, y0 = threadIdx.y;
#pragma unroll
    for (int i = 0; i < 32; i += 8)
        t[y0 + i][x] = in[(size_t)(br + y0 + i) * C + bc + x];
    __syncthreads();
#pragma unroll
    for (int i = 0; i < 32; i += 8)
        out[(size_t)(bc + y0 + i) * R + br + x] = t[x][y0 + i];
}

// ---------------------------------------------------------------------------
// TF32 GEMM: C[M][N] = A[M][K] @ Bt[N][K]^T + bias   (block 128x128, kc=32)
// ---------------------------------------------------------------------------
__global__ __launch_bounds__(256, 2) void gemm_tf32(
    const float* __restrict__ A, const float* __restrict__ Bt,
    const float* __restrict__ bias, float* __restrict__ C,
    int M, int N, int K)
{
    __shared__ __align__(16) float As[128][36];   // 144B row stride (16B mult)
    __shared__ __align__(16) float Bs[128][36];

    const int tid = threadIdx.x, lane = tid & 31, wid = tid >> 5;
    const int wm = (wid >> 1) * 32;   // 4 warps along M
    const int wn = (wid & 1) * 64;    // 2 warps along N
    const int bm = blockIdx.y * 128, bn = blockIdx.x * 128;

    float acc[2][8][4];
#pragma unroll
    for (int i = 0; i < 2; i++)
#pragma unroll
        for (int j = 0; j < 8; j++)
#pragma unroll
            for (int r = 0; r < 4; r++) acc[i][j][r] = 0.0f;

    const int crow = tid >> 3;            // 0..31
    const int ccol = (tid & 7) * 4;       // 0..28

    const int la_row = ((lane >> 3) & 1) * 8 + (lane & 7);
    const int la_col = ((lane >> 4) & 1) * 4;
    const int lb_row = ((lane >> 4) & 1) * 8 + (lane & 7);
    const int lb_col = ((lane >> 3) & 1) * 4;

    for (int k0 = 0; k0 < K; k0 += 32) {
        __syncthreads();
#pragma unroll
        for (int p = 0; p < 4; p++) {
            const int r = crow + p * 32;
            float4 av = *(const float4*)(A + (size_t)(bm + r) * K + k0 + ccol);
            av.x = f2tf(av.x); av.y = f2tf(av.y); av.z = f2tf(av.z); av.w = f2tf(av.w);
            *(float4*)&As[r][ccol] = av;
            float4 bv = *(const float4*)(Bt + (size_t)(bn + r) * K + k0 + ccol);
            bv.x = f2tf(bv.x); bv.y = f2tf(bv.y); bv.z = f2tf(bv.z); bv.w = f2tf(bv.w);
            *(float4*)&Bs[r][ccol] = bv;
        }
        __syncthreads();

#pragma unroll
        for (int ks = 0; ks < 4; ks++) {
            uint32_t a[2][4];
#pragma unroll
            for (int mf = 0; mf < 2; mf++)
                ldsm4(a[mf][0], a[mf][1], a[mf][2], a[mf][3],
                      &As[wm + mf * 16 + la_row][ks * 8 + la_col]);
#pragma unroll
            for (int np = 0; np < 4; np++) {
                uint32_t b0, b1, b2, b3;
                ldsm4(b0, b1, b2, b3, &Bs[wn + np * 16 + lb_row][ks * 8 + lb_col]);
                mma8(acc[0][2 * np],     a[0], b0, b1);
                mma8(acc[0][2 * np + 1], a[0], b2, b3);
                mma8(acc[1][2 * np],     a[1], b0, b1);
                mma8(acc[1][2 * np + 1], a[1], b2, b3);
            }
        }
    }

    const int r0 = bm + wm + (lane >> 2);
    const int c0 = bn + wn + (lane & 3) * 2;
#pragma unroll
    for (int mf = 0; mf < 2; mf++)
#pragma unroll
        for (int nf = 0; nf < 8; nf++) {
            const int row = r0 + mf * 16;
            const int col = c0 + nf * 8;
            const float bx = bias[col], by = bias[col + 1];
            float2 v01 = make_float2(acc[mf][nf][0] + bx, acc[mf][nf][1] + by);
            float2 v23 = make_float2(acc[mf][nf][2] + bx, acc[mf][nf][3] + by);
            *(float2*)&C[(size_t)row * N + col] = v01;
            *(float2*)&C[(size_t)(row + 8) * N + col] = v23;
        }
}

// ---------------------------------------------------------------------------
// RoPE + permute. Block = (head, 32 seq rows). Writes Q,K [h][s][d] (Q scaled),
// V transposed [h][d][s].  Smem rows padded to 68 floats (272B = 16B mult).
// ---------------------------------------------------------------------------
__global__ __launch_bounds__(256) void rope_kernel(
    const float* __restrict__ cosp, const float* __restrict__ sinp)
{
    __shared__ __align__(16) float qs[32][68], ks2[32][68], vs[32][68];
    const int h = blockIdx.y;
    const int s0 = blockIdx.x * 32;
    const int tid = threadIdx.x;
    const int r = tid >> 3;           // 0..31
    const int cb = (tid & 7) * 4;     // 0..28

#pragma unroll
    for (int p = 0; p < 2; p++) {
        const int c = cb + 32 * p;
        const size_t base = (size_t)(s0 + r) * (3 * HID) + h * HD + c;
        *(float4*)&qs[r][c]  = *(const float4*)&g_qkv[base];
        *(float4*)&ks2[r][c] = *(const float4*)&g_qkv[base + HID];
        *(float4*)&vs[r][c]  = *(const float4*)&g_qkv[base + 2 * HID];
    }
    __syncthreads();

#pragma unroll
    for (int p = 0; p < 2; p++) {
        const int c = cb + 32 * p;
        const float4 cv = *(const float4*)&cosp[(s0 + r) * HD + c];
        const float4 sv = *(const float4*)&sinp[(s0 + r) * HD + c];
        const float sign = (c < 32) ? -1.0f : 1.0f;
        const int cp = c ^ 32;
        float4 qo, ko;
        qo.x = (qs[r][c + 0] * cv.x + sign * qs[r][cp + 0] * sv.x) * 0.125f;
        qo.y = (qs[r][c + 1] * cv.y + sign * qs[r][cp + 1] * sv.y) * 0.125f;
        qo.z = (qs[r][c + 2] * cv.z + sign * qs[r][cp + 2] * sv.z) * 0.125f;
        qo.w = (qs[r][c + 3] * cv.w + sign * qs[r][cp + 3] * sv.w) * 0.125f;
        ko.x = ks2[r][c + 0] * cv.x + sign * ks2[r][cp + 0] * sv.x;
        ko.y = ks2[r][c + 1] * cv.y + sign * ks2[r][cp + 1] * sv.y;
        ko.z = ks2[r][c + 2] * cv.z + sign * ks2[r][cp + 2] * sv.z;
        ko.w = ks2[r][c + 3] * cv.w + sign * ks2[r][cp + 3] * sv.w;
        const size_t o = ((size_t)h * SEQ + s0 + r) * HD + c;
        *(float4*)&g_Q[o] = qo;
        *(float4*)&g_K[o] = ko;
    }

    // V transpose: [h][d][s]
#pragma unroll
    for (int p = 0; p < 2; p++) {
        const int d = (tid >> 3) + 32 * p;
        const int s4 = (tid & 7) * 4;
        float4 vv = make_float4(vs[s4][d], vs[s4 + 1][d], vs[s4 + 2][d], vs[s4 + 3][d]);
        *(float4*)&g_Vt[(size_t)h * HD * SEQ + (size_t)d * SEQ + s0 + s4] = vv;
    }
}

// ---------------------------------------------------------------------------
// Flash attention, tf32 mma. Block = (head, 128 q-rows), 8 warps (m16 each).
// ---------------------------------------------------------------------------
__global__ __launch_bounds__(256, 1) void flash_tf32()
{
    __shared__ __align__(16) float sm[128][68];   // rows 0-63: Ks[c][d], 64-127: Vs[d][c]
    float (*Ks)[68] = sm;
    float (*Vs)[68] = sm + 64;

    const int tid = threadIdx.x, lane = tid & 31, wid = tid >> 5;
    const int h = blockIdx.y, qb = blockIdx.x;

    const float* Qg  = g_Q  + ((size_t)h * SEQ + qb * 128) * HD;
    const float* Kg  = g_K  + (size_t)h * SEQ * HD;
    const float* Vtg = g_Vt + (size_t)h * HD * SEQ;

    // --- stage Q (128x64) into sm, convert to tf32 ---
    {
        const int r = tid >> 1;
        const int cb = (tid & 1) * 32;
#pragma unroll
        for (int j = 0; j < 8; j++) {
            const int c = cb + j * 4;
            float4 q = *(const float4*)(Qg + (size_t)r * HD + c);
            q.x = f2tf(q.x); q.y = f2tf(q.y); q.z = f2tf(q.z); q.w = f2tf(q.w);
            *(float4*)&sm[r][c] = q;
        }
    }
    __syncthreads();

    // --- Q fragments to registers ---
    uint32_t qf[8][4];
    {
        const int qrow = wid * 16 + ((lane >> 3) & 1) * 8 + (lane & 7);
        const int qcol = ((lane >> 4) & 1) * 4;
#pragma unroll
        for (int ks = 0; ks < 8; ks++)
            ldsm4(qf[ks][0], qf[ks][1], qf[ks][2], qf[ks][3], &sm[qrow][ks * 8 + qcol]);
    }
    __syncthreads();

    float o[8][4];
#pragma unroll
    for (int i = 0; i < 8; i++)
#pragma unroll
        for (int j = 0; j < 4; j++) o[i][j] = 0.0f;
    float mA = -INFINITY, mB = -INFINITY, lA = 0.0f, lB = 0.0f;

    const int lb_row = ((lane >> 4) & 1) * 8 + (lane & 7);
    const int lb_col = ((lane >> 3) & 1) * 4;

    const int cr = tid >> 2;              // 0..63 copy row
    const int ccb = (tid & 3) * 16;       // copy col base

    const int q4 = lane & 3;
    const int psrc = (lane & ~3) | (q4 >> 1);
    const bool podd = q4 & 1;

    for (int jt = 0; jt < SEQ / 64; jt++) {
        __syncthreads();
        // load K tile [c][d] and V tile [d][c] (tf32-converted)
#pragma unroll
        for (int j = 0; j < 4; j++) {
            const int c = ccb + j * 4;
            float4 kv = *(const float4*)(Kg + (size_t)(jt * 64 + cr) * HD + c);
            kv.x = f2tf(kv.x); kv.y = f2tf(kv.y); kv.z = f2tf(kv.z); kv.w = f2tf(kv.w);
            *(float4*)&Ks[cr][c] = kv;
            float4 vv = *(const float4*)(Vtg + (size_t)cr * SEQ + jt * 64 + c);
            vv.x = f2tf(vv.x); vv.y = f2tf(vv.y); vv.z = f2tf(vv.z); vv.w = f2tf(vv.w);
            *(float4*)&Vs[cr][c] = vv;
        }
        __syncthreads();

        // S = Q @ K^T
        float s[8][4];
#pragma unroll
        for (int i = 0; i < 8; i++)
#pragma unroll
            for (int j = 0; j < 4; j++) s[i][j] = 0.0f;

#pragma unroll
        for (int ks = 0; ks < 8; ks++) {
#pragma unroll
            for (int cfp = 0; cfp < 4; cfp++) {
                uint32_t b0, b1, b2, b3;
                ldsm4(b0, b1, b2, b3, &Ks[cfp * 16 + lb_row][ks * 8 + lb_col]);
                mma8(s[2 * cfp],     qf[ks], b0, b1);
                mma8(s[2 * cfp + 1], qf[ks], b2, b3);
            }
        }

        // online softmax
        float mtA = -INFINITY, mtB = -INFINITY;
#pragma unroll
        for (int nf = 0; nf < 8; nf++) {
            mtA = fmaxf(mtA, fmaxf(s[nf][0], s[nf][1]));
            mtB = fmaxf(mtB, fmaxf(s[nf][2], s[nf][3]));
        }
#pragma unroll
        for (int off = 1; off < 4; off <<= 1) {
            mtA = fmaxf(mtA, __shfl_xor_sync(0xffffffffu, mtA, off));
            mtB = fmaxf(mtB, __shfl_xor_sync(0xffffffffu, mtB, off));
        }
        const float mnA = fmaxf(mA, mtA), mnB = fmaxf(mB, mtB);
        const float aA = __expf(mA - mnA), aB = __expf(mB - mnB);
        mA = mnA; mB = mnB;
        float sA = 0.0f, sB = 0.0f;
#pragma unroll
        for (int nf = 0; nf < 8; nf++) {
            s[nf][0] = __expf(s[nf][0] - mnA); sA += s[nf][0];
            s[nf][1] = __expf(s[nf][1] - mnA); sA += s[nf][1];
            s[nf][2] = __expf(s[nf][2] - mnB); sB += s[nf][2];
            s[nf][3] = __expf(s[nf][3] - mnB); sB += s[nf][3];
        }
#pragma unroll
        for (int off = 1; off < 4; off <<= 1) {
            sA += __shfl_xor_sync(0xffffffffu, sA, off);
            sB += __shfl_xor_sync(0xffffffffu, sB, off);
        }
        lA = lA * aA + sA;
        lB = lB * aB + sB;
#pragma unroll
        for (int df = 0; df < 8; df++) {
            o[df][0] *= aA; o[df][1] *= aA;
            o[df][2] *= aB; o[df][3] *= aB;
        }

        // permute P (accum layout) -> A-fragment layout, convert to tf32, in place
#pragma unroll
        for (int nf = 0; nf < 8; nf++) {
            float t00 = __shfl_sync(0xffffffffu, s[nf][0], psrc);
            float t01 = __shfl_sync(0xffffffffu, s[nf][1], psrc);
            float t10 = __shfl_sync(0xffffffffu, s[nf][2], psrc);
            float t11 = __shfl_sync(0xffffffffu, s[nf][3], psrc);
            float u00 = __shfl_sync(0xffffffffu, s[nf][0], psrc + 2);
            float u01 = __shfl_sync(0xffffffffu, s[nf][1], psrc + 2);
            float u10 = __shfl_sync(0xffffffffu, s[nf][2], psrc + 2);
            float u11 = __shfl_sync(0xffffffffu, s[nf][3], psrc + 2);
            s[nf][0] = __uint_as_float(f2tf_u(podd ? t01 : t00));
            s[nf][1] = __uint_as_float(f2tf_u(podd ? t11 : t10));
            s[nf][2] = __uint_as_float(f2tf_u(podd ? u01 : u00));
            s[nf][3] = __uint_as_float(f2tf_u(podd ? u11 : u10));
        }

        // O += P @ V
#pragma unroll
        for (int cf = 0; cf < 8; cf++) {
            uint32_t pa[4] = {__float_as_uint(s[cf][0]), __float_as_uint(s[cf][1]),
                              __float_as_uint(s[cf][2]), __float_as_uint(s[cf][3])};
#pragma unroll
            for (int dfp = 0; dfp < 4; dfp++) {
                uint32_t b0, b1, b2, b3;
                ldsm4(b0, b1, b2, b3, &Vs[dfp * 16 + lb_row][cf * 8 + lb_col]);
                mma8(o[2 * dfp],     pa, b0, b1);
                mma8(o[2 * dfp + 1], pa, b2, b3);
            }
        }
    }

    // epilogue: normalize, write ctx[s][h*64+d]
    const float irA = 1.0f / lA, irB = 1.0f / lB;
    const int rowA = qb * 128 + wid * 16 + (lane >> 2);
    const int colb = h * HD + (lane & 3) * 2;
#pragma unroll
    for (int df = 0; df < 8; df++) {
        const int col = colb + df * 8;
        float2 vA = make_float2(o[df][0] * irA, o[df][1] * irA);
        float2 vB = make_float2(o[df][2] * irB, o[df][3] * irB);
        *(float2*)&g_ctx[(size_t)rowA * HID + col] = vA;
        *(float2*)&g_ctx[(size_t)(rowA + 8) * HID + col] = vB;
    }
}

// ---------------------------------------------------------------------------
// kernel_launch
// Inputs: hidden_states, cu_seqlens(unused), cos, sin, W_qkv, b_qkv, W_proj, b_proj
// ---------------------------------------------------------------------------
extern "C" void kernel_launch(void* const* d_in, const int* in_sizes, int n_in,
                              void* d_out, int out_size)
{
    const float* hs    = (const float*)d_in[0];
    const float* cosp  = (const float*)d_in[2];
    const float* sinp  = (const float*)d_in[3];
    const float* Wqkv  = (const float*)d_in[4];
    const float* bqkv  = (const float*)d_in[5];
    const float* Wproj = (const float*)d_in[6];
    const float* bproj = (const float*)d_in[7];
    float* out = (float*)d_out;

    float *qkv_p, *ctx_p, *wqt_p, *wpt_p;
    cudaGetSymbolAddress((void**)&qkv_p, g_qkv);
    cudaGetSymbolAddress((void**)&ctx_p, g_ctx);
    cudaGetSymbolAddress((void**)&wqt_p, g_WqkvT);
    cudaGetSymbolAddress((void**)&wpt_p, g_WprojT);

    dim3 tb(32, 8);
    transpose_kernel<<<dim3(3 * HID / 32, HID / 32), tb>>>(Wqkv, wqt_p, HID, 3 * HID);
    transpose_kernel<<<dim3(HID / 32, HID / 32), tb>>>(Wproj, wpt_p, HID, HID);

    gemm_tf32<<<dim3(3 * HID / 128, SEQ / 128), 256>>>(hs, wqt_p, bqkv, qkv_p,
                                                       SEQ, 3 * HID, HID);
    rope_kernel<<<dim3(SEQ / 32, NH), 256>>>(cosp, sinp);
    flash_tf32<<<dim3(SEQ / 128, NH), 256>>>();
    gemm_tf32<<<dim3(HID / 128, SEQ / 128), 256>>>(ctx_p, wpt_p, bproj, out,
                                                   SEQ, HID, HID);
}

// round 4
// speedup vs baseline: 2.8247x; 1.0564x over previous
#include <cuda_runtime.h>
#include <math.h>
#include <stdint.h>

#define SEQ  4096
#define NH   16
#define HD   64
#define HID  1024

// Scratch (no allocation allowed) — device globals.
__device__ float g_qkv[SEQ * 3 * HID];
__device__ float g_hsr[SEQ * HID];       // tf32-rounded hidden_states
__device__ float g_Q[NH * SEQ * HD];     // [h][s][d]  (rounded, scaled)
__device__ float g_K[NH * SEQ * HD];     // [h][s][d]  (rounded)
__device__ float g_Vt[NH * HD * SEQ];    // [h][d][s]  (rounded)
__device__ float g_ctx[SEQ * HID];       // rounded
__device__ float g_WqkvT[3 * HID * HID]; // [n][k] rounded
__device__ float g_WprojT[HID * HID];    // [n][k] rounded

// ---------------- helpers ----------------
__device__ __forceinline__ uint32_t f2tf_u(float x) {
    uint32_t r;
    asm("cvt.rna.tf32.f32 %0, %1;" : "=r"(r) : "f"(x));
    return r;
}
__device__ __forceinline__ float f2tf(float x) { return __uint_as_float(f2tf_u(x)); }

__device__ __forceinline__ float ex2(float x) {
    float y;
    asm("ex2.approx.f32 %0, %1;" : "=f"(y) : "f"(x));
    return y;
}

__device__ __forceinline__ void ldsm4(uint32_t& r0, uint32_t& r1, uint32_t& r2, uint32_t& r3,
                                      const void* p) {
    uint32_t addr = (uint32_t)__cvta_generic_to_shared(p);
    asm volatile("ldmatrix.sync.aligned.m8n8.x4.shared.b16 {%0,%1,%2,%3}, [%4];"
                 : "=r"(r0), "=r"(r1), "=r"(r2), "=r"(r3) : "r"(addr));
}

__device__ __forceinline__ void mma8(float c[4], const uint32_t a[4], uint32_t b0, uint32_t b1) {
    asm volatile(
        "mma.sync.aligned.m16n8k8.row.col.f32.tf32.tf32.f32 "
        "{%0,%1,%2,%3}, {%4,%5,%6,%7}, {%8,%9}, {%0,%1,%2,%3};"
        : "+f"(c[0]), "+f"(c[1]), "+f"(c[2]), "+f"(c[3])
        : "r"(a[0]), "r"(a[1]), "r"(a[2]), "r"(a[3]), "r"(b0), "r"(b1));
}

__device__ __forceinline__ void cpa16(void* dst, const void* src) {
    uint32_t d = (uint32_t)__cvta_generic_to_shared(dst);
    asm volatile("cp.async.cg.shared.global [%0], [%1], 16;" :: "r"(d), "l"(src));
}
__device__ __forceinline__ void cp_commit() {
    asm volatile("cp.async.commit_group;");
}
template <int N>
__device__ __forceinline__ void cp_wait() {
    asm volatile("cp.async.wait_group %0;" :: "n"(N));
}

#define LOG2E 1.4426950408889634f

// ---------------------------------------------------------------------------
// Round hidden_states to tf32 (elementwise copy)
// ---------------------------------------------------------------------------
__global__ __launch_bounds__(256) void round_hs_kernel(const float* __restrict__ in) {
    const int i = (blockIdx.x * 256 + threadIdx.x) * 4;
    float4 v = *(const float4*)(in + i);
    v.x = f2tf(v.x); v.y = f2tf(v.y); v.z = f2tf(v.z); v.w = f2tf(v.w);
    *(float4*)&g_hsr[i] = v;
}

// ---------------------------------------------------------------------------
// Transpose + tf32 round: out[c][r] = tf32(in[r][c])
// ---------------------------------------------------------------------------
__global__ void transpose_kernel(const float* __restrict__ in, float* __restrict__ out,
                                 int R, int C) {
    __shared__ float t[32][33];
    const int bc = blockIdx.x * 32, br = blockIdx.y * 32;
    const int x = threadIdx.x, y0 = threadIdx.y;
#pragma unroll
    for (int i = 0; i < 32; i += 8)
        t[y0 + i][x] = in[(size_t)(br + y0 + i) * C + bc + x];
    __syncthreads();
#pragma unroll
    for (int i = 0; i < 32; i += 8)
        out[(size_t)(bc + y0 + i) * R + br + x] = f2tf(t[x][y0 + i]);
}

// ---------------------------------------------------------------------------
// TF32 GEMM (cp.async 2-stage): C = A[M,K] @ Bt[N,K]^T + bias
// A, Bt already tf32-rounded. kc = 32. Dynamic smem: 2 stages * (As+Bs).
// ---------------------------------------------------------------------------
#define GSTG (128 * 36)
__global__ __launch_bounds__(256, 2) void gemm_tf32(
    const float* __restrict__ A, const float* __restrict__ Bt,
    const float* __restrict__ bias, float* __restrict__ C,
    int M, int N, int K)
{
    extern __shared__ __align__(16) float gsm[];   // [2][2*GSTG]

    const int tid = threadIdx.x, lane = tid & 31, wid = tid >> 5;
    const int wm = (wid >> 1) * 32;
    const int wn = (wid & 1) * 64;
    const int bm = blockIdx.y * 128, bn = blockIdx.x * 128;

    float acc[2][8][4];
#pragma unroll
    for (int i = 0; i < 2; i++)
#pragma unroll
        for (int j = 0; j < 8; j++)
#pragma unroll
            for (int r = 0; r < 4; r++) acc[i][j][r] = 0.0f;

    // cp.async mapping: row = tid>>1 (0..127), 4 chunks at cols (tid&1)*16 + 4j
    const int crow = tid >> 1;
    const int ccol = (tid & 1) * 16;
    const float* Arow = A  + (size_t)(bm + crow) * K + ccol;
    const float* Brow = Bt + (size_t)(bn + crow) * K + ccol;

    const int la_row = ((lane >> 3) & 1) * 8 + (lane & 7);
    const int la_col = ((lane >> 4) & 1) * 4;
    const int lb_row = ((lane >> 4) & 1) * 8 + (lane & 7);
    const int lb_col = ((lane >> 3) & 1) * 4;

    const int NIT = K / 32;

    // prologue: stages 0,1
#pragma unroll
    for (int p = 0; p < 2; p++) {
        float* As = gsm + p * 2 * GSTG;
        float* Bs = As + GSTG;
#pragma unroll
        for (int j = 0; j < 4; j++) {
            cpa16(&As[crow * 36 + ccol + j * 4], Arow + p * 32 + j * 4);
            cpa16(&Bs[crow * 36 + ccol + j * 4], Brow + p * 32 + j * 4);
        }
        cp_commit();
    }

    for (int it = 0; it < NIT; it++) {
        cp_wait<1>();
        __syncthreads();
        float* As = gsm + (it & 1) * 2 * GSTG;
        float* Bs = As + GSTG;

#pragma unroll
        for (int ks = 0; ks < 4; ks++) {
            uint32_t a[2][4];
#pragma unroll
            for (int mf = 0; mf < 2; mf++)
                ldsm4(a[mf][0], a[mf][1], a[mf][2], a[mf][3],
                      &As[(wm + mf * 16 + la_row) * 36 + ks * 8 + la_col]);
#pragma unroll
            for (int np = 0; np < 4; np++) {
                uint32_t b0, b1, b2, b3;
                ldsm4(b0, b1, b2, b3, &Bs[(wn + np * 16 + lb_row) * 36 + ks * 8 + lb_col]);
                mma8(acc[0][2 * np],     a[0], b0, b1);
                mma8(acc[0][2 * np + 1], a[0], b2, b3);
                mma8(acc[1][2 * np],     a[1], b0, b1);
                mma8(acc[1][2 * np + 1], a[1], b2, b3);
            }
        }
        __syncthreads();
        if (it + 2 < NIT) {
            float* Asn = gsm + (it & 1) * 2 * GSTG;
            float* Bsn = Asn + GSTG;
            const int k0 = (it + 2) * 32;
#pragma unroll
            for (int j = 0; j < 4; j++) {
                cpa16(&Asn[crow * 36 + ccol + j * 4], Arow + k0 + j * 4);
                cpa16(&Bsn[crow * 36 + ccol + j * 4], Brow + k0 + j * 4);
            }
            cp_commit();
        }
    }

    const int r0 = bm + wm + (lane >> 2);
    const int c0 = bn + wn + (lane & 3) * 2;
#pragma unroll
    for (int mf = 0; mf < 2; mf++)
#pragma unroll
        for (int nf = 0; nf < 8; nf++) {
            const int row = r0 + mf * 16;
            const int col = c0 + nf * 8;
            const float bx = bias[col], by = bias[col + 1];
            float2 v01 = make_float2(acc[mf][nf][0] + bx, acc[mf][nf][1] + by);
            float2 v23 = make_float2(acc[mf][nf][2] + bx, acc[mf][nf][3] + by);
            *(float2*)&C[(size_t)row * N + col] = v01;
            *(float2*)&C[(size_t)(row + 8) * N + col] = v23;
        }
}

// ---------------------------------------------------------------------------
// RoPE + permute + tf32 round. Q scaled by 0.125*log2(e) (exp2-domain softmax).
// ---------------------------------------------------------------------------
__global__ __launch_bounds__(256) void rope_kernel(
    const float* __restrict__ cosp, const float* __restrict__ sinp)
{
    __shared__ __align__(16) float qs[32][68], ks2[32][68], vs[32][68];
    const int h = blockIdx.y;
    const int s0 = blockIdx.x * 32;
    const int tid = threadIdx.x;
    const int r = tid >> 3;
    const int cb = (tid & 7) * 4;

#pragma unroll
    for (int p = 0; p < 2; p++) {
        const int c = cb + 32 * p;
        const size_t base = (size_t)(s0 + r) * (3 * HID) + h * HD + c;
        *(float4*)&qs[r][c]  = *(const float4*)&g_qkv[base];
        *(float4*)&ks2[r][c] = *(const float4*)&g_qkv[base + HID];
        *(float4*)&vs[r][c]  = *(const float4*)&g_qkv[base + 2 * HID];
    }
    __syncthreads();

    const float qscale = 0.125f * LOG2E;
#pragma unroll
    for (int p = 0; p < 2; p++) {
        const int c = cb + 32 * p;
        const float4 cv = *(const float4*)&cosp[(s0 + r) * HD + c];
        const float4 sv = *(const float4*)&sinp[(s0 + r) * HD + c];
        const float sign = (c < 32) ? -1.0f : 1.0f;
        const int cp = c ^ 32;
        float4 qo, ko;
        qo.x = f2tf((qs[r][c + 0] * cv.x + sign * qs[r][cp + 0] * sv.x) * qscale);
        qo.y = f2tf((qs[r][c + 1] * cv.y + sign * qs[r][cp + 1] * sv.y) * qscale);
        qo.z = f2tf((qs[r][c + 2] * cv.z + sign * qs[r][cp + 2] * sv.z) * qscale);
        qo.w = f2tf((qs[r][c + 3] * cv.w + sign * qs[r][cp + 3] * sv.w) * qscale);
        ko.x = f2tf(ks2[r][c + 0] * cv.x + sign * ks2[r][cp + 0] * sv.x);
        ko.y = f2tf(ks2[r][c + 1] * cv.y + sign * ks2[r][cp + 1] * sv.y);
        ko.z = f2tf(ks2[r][c + 2] * cv.z + sign * ks2[r][cp + 2] * sv.z);
        ko.w = f2tf(ks2[r][c + 3] * cv.w + sign * ks2[r][cp + 3] * sv.w);
        const size_t o = ((size_t)h * SEQ + s0 + r) * HD + c;
        *(float4*)&g_Q[o] = qo;
        *(float4*)&g_K[o] = ko;
    }

    // V transpose (rounded): [h][d][s]
#pragma unroll
    for (int p = 0; p < 2; p++) {
        const int d = (tid >> 3) + 32 * p;
        const int s4 = (tid & 7) * 4;
        float4 vv = make_float4(f2tf(vs[s4][d]), f2tf(vs[s4 + 1][d]),
                                f2tf(vs[s4 + 2][d]), f2tf(vs[s4 + 3][d]));
        *(float4*)&g_Vt[(size_t)h * HD * SEQ + (size_t)d * SEQ + s0 + s4] = vv;
    }
}

// ---------------------------------------------------------------------------
// Flash attention, tf32 mma, cp.async 2-stage K/V pipeline.
// Block = (head, 128 q-rows), 8 warps. Dynamic smem: 2 stages * (K+V tile).
// Stage = 64x68 K + 64x68 V = 8704 floats. Q staged temporarily in stage 0.
// ---------------------------------------------------------------------------
#define FSTG  8704          // floats per stage (K tile + V tile)
#define FKV   4352          // floats per tile (64*68)

__global__ __launch_bounds__(256) void flash_tf32()
{
    extern __shared__ __align__(16) float fsm[];   // 2*FSTG floats

    const int tid = threadIdx.x, lane = tid & 31, wid = tid >> 5;
    const int h = blockIdx.y, qb = blockIdx.x;

    const float* Qg  = g_Q  + ((size_t)h * SEQ + qb * 128) * HD;
    const float* Kg  = g_K  + (size_t)h * SEQ * HD;
    const float* Vtg = g_Vt + (size_t)h * HD * SEQ;

    // --- stage Q (128x64, pre-rounded) into fsm[0..8704) ---
    {
        const int r = tid >> 1;
        const int cb = (tid & 1) * 32;
#pragma unroll
        for (int j = 0; j < 8; j++)
            *(float4*)&fsm[r * 68 + cb + j * 4] = *(const float4*)(Qg + (size_t)r * HD + cb + j * 4);
    }
    __syncwarp();   // warp w wrote rows 16w..16w+15 and reads only those rows

    uint32_t qf[8][4];
    {
        const int qrow = wid * 16 + ((lane >> 3) & 1) * 8 + (lane & 7);
        const int qcol = ((lane >> 4) & 1) * 4;
#pragma unroll
        for (int ks = 0; ks < 8; ks++)
            ldsm4(qf[ks][0], qf[ks][1], qf[ks][2], qf[ks][3],
                  &fsm[qrow * 68 + ks * 8 + qcol]);
    }
    __syncthreads();   // Q consumed; stage 0 free for the pipeline

    // cp.async mapping for K/V tiles: row cr = tid>>2, cols (tid&3)*16 + 4j
    const int cr = tid >> 2;
    const int cc = (tid & 3) * 16;

    // prologue: tiles 0,1
#pragma unroll
    for (int p = 0; p < 2; p++) {
        float* Kst = fsm + p * FSTG;
        float* Vst = Kst + FKV;
#pragma unroll
        for (int j = 0; j < 4; j++) {
            cpa16(&Kst[cr * 68 + cc + j * 4], Kg + (size_t)(p * 64 + cr) * HD + cc + j * 4);
            cpa16(&Vst[cr * 68 + cc + j * 4], Vtg + (size_t)cr * SEQ + p * 64 + cc + j * 4);
        }
        cp_commit();
    }

    float o[8][4];
#pragma unroll
    for (int i = 0; i < 8; i++)
#pragma unroll
        for (int j = 0; j < 4; j++) o[i][j] = 0.0f;
    float mA = -INFINITY, mB = -INFINITY, lA = 0.0f, lB = 0.0f;

    const int lb_row = ((lane >> 4) & 1) * 8 + (lane & 7);
    const int lb_col = ((lane >> 3) & 1) * 4;

    const int q4 = lane & 3;
    const int psrc = (lane & ~3) | (q4 >> 1);
    const bool podd = q4 & 1;

    for (int jt = 0; jt < SEQ / 64; jt++) {
        cp_wait<1>();
        __syncthreads();
        float* Kst = fsm + (jt & 1) * FSTG;
        float* Vst = Kst + FKV;

        // S = Q @ K^T   (log2-domain: scale folded into Q)
        float s[8][4];
#pragma unroll
        for (int i = 0; i < 8; i++)
#pragma unroll
            for (int j = 0; j < 4; j++) s[i][j] = 0.0f;

#pragma unroll
        for (int ks = 0; ks < 8; ks++) {
#pragma unroll
            for (int cfp = 0; cfp < 4; cfp++) {
                uint32_t b0, b1, b2, b3;
                ldsm4(b0, b1, b2, b3, &Kst[(cfp * 16 + lb_row) * 68 + ks * 8 + lb_col]);
                mma8(s[2 * cfp],     qf[ks], b0, b1);
                mma8(s[2 * cfp + 1], qf[ks], b2, b3);
            }
        }

        // online softmax (exp2 domain)
        float mtA = -INFINITY, mtB = -INFINITY;
#pragma unroll
        for (int nf = 0; nf < 8; nf++) {
            mtA = fmaxf(mtA, fmaxf(s[nf][0], s[nf][1]));
            mtB = fmaxf(mtB, fmaxf(s[nf][2], s[nf][3]));
        }
#pragma unroll
        for (int off = 1; off < 4; off <<= 1) {
            mtA = fmaxf(mtA, __shfl_xor_sync(0xffffffffu, mtA, off));
            mtB = fmaxf(mtB, __shfl_xor_sync(0xffffffffu, mtB, off));
        }
        const float mnA = fmaxf(mA, mtA), mnB = fmaxf(mB, mtB);
        const float aA = ex2(mA - mnA), aB = ex2(mB - mnB);
        mA = mnA; mB = mnB;
        float sA = 0.0f, sB = 0.0f;
#pragma unroll
        for (int nf = 0; nf < 8; nf++) {
            s[nf][0] = ex2(s[nf][0] - mnA); sA += s[nf][0];
            s[nf][1] = ex2(s[nf][1] - mnA); sA += s[nf][1];
            s[nf][2] = ex2(s[nf][2] - mnB); sB += s[nf][2];
            s[nf][3] = ex2(s[nf][3] - mnB); sB += s[nf][3];
        }
#pragma unroll
        for (int off = 1; off < 4; off <<= 1) {
            sA += __shfl_xor_sync(0xffffffffu, sA, off);
            sB += __shfl_xor_sync(0xffffffffu, sB, off);
        }
        lA = lA * aA + sA;
        lB = lB * aB + sB;
#pragma unroll
        for (int df = 0; df < 8; df++) {
            o[df][0] *= aA; o[df][1] *= aA;
            o[df][2] *= aB; o[df][3] *= aB;
        }

        // permute P (accum layout) -> A-fragment layout, tf32-round
#pragma unroll
        for (int nf = 0; nf < 8; nf++) {
            float t00 = __shfl_sync(0xffffffffu, s[nf][0], psrc);
            float t01 = __shfl_sync(0xffffffffu, s[nf][1], psrc);
            float t10 = __shfl_sync(0xffffffffu, s[nf][2], psrc);
            float t11 = __shfl_sync(0xffffffffu, s[nf][3], psrc);
            float u00 = __shfl_sync(0xffffffffu, s[nf][0], psrc + 2);
            float u01 = __shfl_sync(0xffffffffu, s[nf][1], psrc + 2);
            float u10 = __shfl_sync(0xffffffffu, s[nf][2], psrc + 2);
            float u11 = __shfl_sync(0xffffffffu, s[nf][3], psrc + 2);
            s[nf][0] = __uint_as_float(f2tf_u(podd ? t01 : t00));
            s[nf][1] = __uint_as_float(f2tf_u(podd ? t11 : t10));
            s[nf][2] = __uint_as_float(f2tf_u(podd ? u01 : u00));
            s[nf][3] = __uint_as_float(f2tf_u(podd ? u11 : u10));
        }

        // O += P @ V
#pragma unroll
        for (int cf = 0; cf < 8; cf++) {
            uint32_t pa[4] = {__float_as_uint(s[cf][0]), __float_as_uint(s[cf][1]),
                              __float_as_uint(s[cf][2]), __float_as_uint(s[cf][3])};
#pragma unroll
            for (int dfp = 0; dfp < 4; dfp++) {
                uint32_t b0, b1, b2, b3;
                ldsm4(b0, b1, b2, b3, &Vst[(dfp * 16 + lb_row) * 68 + cf * 8 + lb_col]);
                mma8(o[2 * dfp],     pa, b0, b1);
                mma8(o[2 * dfp + 1], pa, b2, b3);
            }
        }

        __syncthreads();
        if (jt + 2 < SEQ / 64) {
            float* Kn = fsm + (jt & 1) * FSTG;
            float* Vn = Kn + FKV;
            const int t2 = jt + 2;
#pragma unroll
            for (int j = 0; j < 4; j++) {
                cpa16(&Kn[cr * 68 + cc + j * 4], Kg + (size_t)(t2 * 64 + cr) * HD + cc + j * 4);
                cpa16(&Vn[cr * 68 + cc + j * 4], Vtg + (size_t)cr * SEQ + t2 * 64 + cc + j * 4);
            }
            cp_commit();
        }
    }

    // epilogue: normalize, tf32-round (feeds proj GEMM), write ctx[s][h*64+d]
    const float irA = 1.0f / lA, irB = 1.0f / lB;
    const int rowA = qb * 128 + wid * 16 + (lane >> 2);
    const int colb = h * HD + (lane & 3) * 2;
#pragma unroll
    for (int df = 0; df < 8; df++) {
        const int col = colb + df * 8;
        float2 vA = make_float2(f2tf(o[df][0] * irA), f2tf(o[df][1] * irA));
        float2 vB = make_float2(f2tf(o[df][2] * irB), f2tf(o[df][3] * irB));
        *(float2*)&g_ctx[(size_t)rowA * HID + col] = vA;
        *(float2*)&g_ctx[(size_t)(rowA + 8) * HID + col] = vB;
    }
}

// ---------------------------------------------------------------------------
// kernel_launch
// Inputs: hidden_states, cu_seqlens(unused), cos, sin, W_qkv, b_qkv, W_proj, b_proj
// ---------------------------------------------------------------------------
extern "C" void kernel_launch(void* const* d_in, const int* in_sizes, int n_in,
                              void* d_out, int out_size)
{
    const float* hs    = (const float*)d_in[0];
    const float* cosp  = (const float*)d_in[2];
    const float* sinp  = (const float*)d_in[3];
    const float* Wqkv  = (const float*)d_in[4];
    const float* bqkv  = (const float*)d_in[5];
    const float* Wproj = (const float*)d_in[6];
    const float* bproj = (const float*)d_in[7];
    float* out = (float*)d_out;

    float *qkv_p, *ctx_p, *wqt_p, *wpt_p, *hsr_p;
    cudaGetSymbolAddress((void**)&qkv_p, g_qkv);
    cudaGetSymbolAddress((void**)&ctx_p, g_ctx);
    cudaGetSymbolAddress((void**)&wqt_p, g_WqkvT);
    cudaGetSymbolAddress((void**)&wpt_p, g_WprojT);
    cudaGetSymbolAddress((void**)&hsr_p, g_hsr);

    const int gemm_smem  = 2 * 2 * GSTG * 4;     // 73,728 B
    const int flash_smem = 2 * FSTG * 4;         // 69,632 B
    cudaFuncSetAttribute(gemm_tf32, cudaFuncAttributeMaxDynamicSharedMemorySize, gemm_smem);
    cudaFuncSetAttribute(flash_tf32, cudaFuncAttributeMaxDynamicSharedMemorySize, flash_smem);

    round_hs_kernel<<<SEQ * HID / (256 * 4), 256>>>(hs);

    dim3 tb(32, 8);
    transpose_kernel<<<dim3(3 * HID / 32, HID / 32), tb>>>(Wqkv, wqt_p, HID, 3 * HID);
    transpose_kernel<<<dim3(HID / 32, HID / 32), tb>>>(Wproj, wpt_p, HID, HID);

    gemm_tf32<<<dim3(3 * HID / 128, SEQ / 128), 256, gemm_smem>>>(
        hsr_p, wqt_p, bqkv, qkv_p, SEQ, 3 * HID, HID);
    rope_kernel<<<dim3(SEQ / 32, NH), 256>>>(cosp, sinp);
    flash_tf32<<<dim3(SEQ / 128, NH), 256, flash_smem>>>();
    gemm_tf32<<<dim3(HID / 128, SEQ / 128), 256, gemm_smem>>>(
        ctx_p, wpt_p, bproj, out, SEQ, HID, HID);
}